// round 9
// baseline (speedup 1.0000x reference)
#include <cuda_runtime.h>
#include <cuda_bf16.h>
#include <stdint.h>

#define N_NODES 50000
#define N_EDGES 800000
#define N_GRAPHS 256
#define DIN0 32
#define HID 96
#define BN_EPS 1e-5f

// ---------------- device scratch (static, allowed) ----------------
__device__ float g_h[(size_t)N_NODES * HID];
__device__ float g_agg[(size_t)N_NODES * HID];
__device__ float g_z[(size_t)N_NODES * HID];
__device__ float g_pool[N_GRAPHS * HID];

// vectorized fire-and-forget global reduction (sm_90+)
__device__ __forceinline__ void red_add_v4(float* addr, float4 v) {
    asm volatile("red.global.add.v4.f32 [%0], {%1, %2, %3, %4};"
                 :: "l"(addr), "f"(v.x), "f"(v.y), "f"(v.z), "f"(v.w)
                 : "memory");
}

__device__ __forceinline__ float to_tf32(float x) {
    uint32_t u;
    asm("cvt.rna.tf32.f32 %0, %1;" : "=r"(u) : "f"(x));
    return __uint_as_float(u);
}

__device__ __forceinline__ void mma_tf32(float* c, uint32_t a0, uint32_t a1,
                                         uint32_t a2, uint32_t a3,
                                         uint32_t b0, uint32_t b1) {
    asm volatile(
        "mma.sync.aligned.m16n8k8.row.col.f32.tf32.tf32.f32 "
        "{%0,%1,%2,%3}, {%4,%5,%6,%7}, {%8,%9}, {%0,%1,%2,%3};"
        : "+f"(c[0]), "+f"(c[1]), "+f"(c[2]), "+f"(c[3])
        : "r"(a0), "r"(a1), "r"(a2), "r"(a3), "r"(b0), "r"(b1));
}

// ---------------- small kernels ----------------
__global__ void copy_x_kernel(const float* __restrict__ x) {
    int i = blockIdx.x * blockDim.x + threadIdx.x;
    int total = N_NODES * DIN0 / 4;
    if (i < total) ((float4*)g_agg)[i] = ((const float4*)x)[i];
}

// edge scatter: agg[dst] += h[src], one red.v4 per (edge, lane)
template<int DIN>
__global__ void edge_kernel(const float* __restrict__ h,
                            const int* __restrict__ ei,
                            float* __restrict__ agg) {
    const int VPR = DIN / 4;
    int t = blockIdx.x * blockDim.x + threadIdx.x;
    int e = t / VPR;
    int lane = t - e * VPR;
    if (e >= N_EDGES) return;
    int s = __ldg(&ei[e]);
    int d = __ldg(&ei[N_EDGES + e]);
    float4 v = *(const float4*)(h + (size_t)s * DIN + lane * 4);
    red_add_v4(agg + (size_t)d * DIN + lane * 4, v);
}

// ---------------- TF32 tensor-core GEMM: out = epi(A[N x DIN] @ W[DIN x 96]) --
// 512 threads = 16 warps. Block tile M=128 x N=96.
// Warp (mw=warp&3, nw=warp>>2): 32-row slab (2 m16 frags) x 24-col slab (3 n8 frags).
// A k-chunks of 8, transposed in smem As[k][row] (stride 136), double-buffered.
// W transposed in smem Wt[n][k] (stride DIN+4).
template<int DIN, bool HAS_BN, bool DUAL>
__global__ void __launch_bounds__(512, 2) gemm_kernel(
    const float* __restrict__ A, const float* __restrict__ W,
    const float* __restrict__ bias,
    const float* __restrict__ gamma, const float* __restrict__ beta,
    const float* __restrict__ rmean, const float* __restrict__ rvar,
    float* __restrict__ out, float* __restrict__ out2)
{
    constexpr int H = 96;
    constexpr int NKC = DIN / 8;
    constexpr int WSTR = DIN + 4;
    __shared__ float Wt[H * WSTR];          // W^T: Wt[n][k]  (38.4KB @ DIN=96)
    __shared__ float As[2][8][136];         // A^T chunk      (8.7KB)

    const int tid  = threadIdx.x;
    const int warp = tid >> 5;
    const int lane = tid & 31;
    const int g    = lane >> 2;             // 0..7
    const int tg   = lane & 3;              // 0..3
    const int mw   = warp & 3;              // 0..3 -> 32-row slab
    const int nw   = warp >> 2;             // 0..3 -> 24-col slab
    const int row0 = blockIdx.x * 128;

    // load W transposed + tf32-rounded
    for (int i = tid; i < DIN * H; i += 512) {
        int k = i / H, n = i - k * H;
        Wt[n * WSTR + k] = to_tf32(W[i]);
    }

    const int r  = tid & 127;               // staging row (tid < 256)
    const int kv = (tid >> 7) & 1;          // staging k sub-offset

    float acc[2][3][4];
    #pragma unroll
    for (int mi = 0; mi < 2; mi++)
        #pragma unroll
        for (int ni = 0; ni < 3; ni++)
            #pragma unroll
            for (int q = 0; q < 4; q++) acc[mi][ni][q] = 0.f;

    // stage chunk 0
    if (tid < 256) {
        int gr = row0 + r;
        float4 v = (gr < N_NODES)
            ? *(const float4*)(A + (size_t)gr * DIN + kv * 4)
            : make_float4(0.f, 0.f, 0.f, 0.f);
        As[0][kv * 4 + 0][r] = to_tf32(v.x);
        As[0][kv * 4 + 1][r] = to_tf32(v.y);
        As[0][kv * 4 + 2][r] = to_tf32(v.z);
        As[0][kv * 4 + 3][r] = to_tf32(v.w);
    }
    __syncthreads();

    int buf = 0;
    for (int kt = 0; kt < NKC; kt++) {
        float4 nv;
        if (kt + 1 < NKC && tid < 256) {
            int gr = row0 + r;
            nv = (gr < N_NODES)
                ? *(const float4*)(A + (size_t)gr * DIN + (kt + 1) * 8 + kv * 4)
                : make_float4(0.f, 0.f, 0.f, 0.f);
        }

        const int kb = kt * 8;
        uint32_t bf[3][2];
        #pragma unroll
        for (int ni = 0; ni < 3; ni++) {
            int n = nw * 24 + ni * 8 + g;
            bf[ni][0] = __float_as_uint(Wt[n * WSTR + kb + tg]);
            bf[ni][1] = __float_as_uint(Wt[n * WSTR + kb + tg + 4]);
        }
        #pragma unroll
        for (int mi = 0; mi < 2; mi++) {
            int ra = mw * 32 + mi * 16 + g;
            uint32_t a0 = __float_as_uint(As[buf][tg][ra]);
            uint32_t a1 = __float_as_uint(As[buf][tg][ra + 8]);
            uint32_t a2 = __float_as_uint(As[buf][tg + 4][ra]);
            uint32_t a3 = __float_as_uint(As[buf][tg + 4][ra + 8]);
            #pragma unroll
            for (int ni = 0; ni < 3; ni++)
                mma_tf32(acc[mi][ni], a0, a1, a2, a3, bf[ni][0], bf[ni][1]);
        }

        if (kt + 1 < NKC) {
            if (tid < 256) {
                As[buf ^ 1][kv * 4 + 0][r] = to_tf32(nv.x);
                As[buf ^ 1][kv * 4 + 1][r] = to_tf32(nv.y);
                As[buf ^ 1][kv * 4 + 2][r] = to_tf32(nv.z);
                As[buf ^ 1][kv * 4 + 3][r] = to_tf32(nv.w);
            }
            __syncthreads();
        }
        buf ^= 1;
    }

    // epilogue: per-thread cols = nw*24 + ni*8 + 2*tg (+1)
    float sc[3][2], sh[3][2];
    #pragma unroll
    for (int ni = 0; ni < 3; ni++)
        #pragma unroll
        for (int jj = 0; jj < 2; jj++) {
            int c = nw * 24 + ni * 8 + 2 * tg + jj;
            if (HAS_BN) {
                float s = gamma[c] * rsqrtf(rvar[c] + BN_EPS);
                sc[ni][jj] = s;
                sh[ni][jj] = (bias[c] - rmean[c]) * s + beta[c];
            } else {
                sc[ni][jj] = 1.f;
                sh[ni][jj] = bias[c];
            }
        }

    #pragma unroll
    for (int mi = 0; mi < 2; mi++) {
        int ra = row0 + mw * 32 + mi * 16 + g;
        int rb = ra + 8;
        #pragma unroll
        for (int ni = 0; ni < 3; ni++) {
            int col = nw * 24 + ni * 8 + 2 * tg;
            if (ra < N_NODES) {
                float2 o;
                o.x = fmaxf(fmaf(acc[mi][ni][0], sc[ni][0], sh[ni][0]), 0.f);
                o.y = fmaxf(fmaf(acc[mi][ni][1], sc[ni][1], sh[ni][1]), 0.f);
                *(float2*)(out + (size_t)ra * H + col) = o;
                if (DUAL) *(float2*)(out2 + (size_t)ra * H + col) = o;
            }
            if (rb < N_NODES) {
                float2 o;
                o.x = fmaxf(fmaf(acc[mi][ni][2], sc[ni][0], sh[ni][0]), 0.f);
                o.y = fmaxf(fmaf(acc[mi][ni][3], sc[ni][1], sh[ni][1]), 0.f);
                *(float2*)(out + (size_t)rb * H + col) = o;
                if (DUAL) *(float2*)(out2 + (size_t)rb * H + col) = o;
            }
        }
    }
}

// ---------------- pooling (batch sorted -> segment sums, no atomics) ----------
__global__ void __launch_bounds__(96) pool_kernel(const int* __restrict__ batch,
                                                  float* __restrict__ pool) {
    int b = blockIdx.x;
    int c = threadIdx.x;
    int lo = 0, hi = N_NODES;
    while (lo < hi) { int m = (lo + hi) >> 1; if (batch[m] < b) lo = m + 1; else hi = m; }
    int start = lo;
    hi = N_NODES;
    while (lo < hi) { int m = (lo + hi) >> 1; if (batch[m] < b + 1) lo = m + 1; else hi = m; }
    int end = lo;

    float acc = 0.f;
    for (int n = start; n < end; n++)
        acc += g_h[(size_t)n * HID + c];
    pool[b * HID + c] = acc;
}

__global__ void head_kernel(const int* __restrict__ r_target,
                            const float* __restrict__ head_w,
                            const float* __restrict__ head_b,
                            const float* __restrict__ pool,
                            float* __restrict__ out) {
    int b = threadIdx.x;
    if (b >= N_GRAPHS) return;
    int t = r_target[b];
    const float4* w = (const float4*)(head_w + (size_t)t * HID);
    const float4* p = (const float4*)(pool + (size_t)b * HID);
    float acc = 0.f;
    #pragma unroll
    for (int k = 0; k < HID / 4; k++) {
        float4 wv = w[k], pv = p[k];
        acc = fmaf(pv.x, wv.x, acc);
        acc = fmaf(pv.y, wv.y, acc);
        acc = fmaf(pv.z, wv.z, acc);
        acc = fmaf(pv.w, wv.w, acc);
    }
    out[b] = acc + head_b[t];
}

// ---------------- launch ----------------
extern "C" void kernel_launch(void* const* d_in, const int* in_sizes, int n_in,
                              void* d_out, int out_size) {
    const float* x    = (const float*)d_in[0];
    const int*   ei   = (const int*)d_in[1];
    const int*   bat  = (const int*)d_in[2];
    const int*   rtg  = (const int*)d_in[3];

    const float* w_in[3]  = {(const float*)d_in[4],  (const float*)d_in[12], (const float*)d_in[20]};
    const float* b_in[3]  = {(const float*)d_in[5],  (const float*)d_in[13], (const float*)d_in[21]};
    const float* gam[3]   = {(const float*)d_in[6],  (const float*)d_in[14], (const float*)d_in[22]};
    const float* bet[3]   = {(const float*)d_in[7],  (const float*)d_in[15], (const float*)d_in[23]};
    const float* rme[3]   = {(const float*)d_in[8],  (const float*)d_in[16], (const float*)d_in[24]};
    const float* rva[3]   = {(const float*)d_in[9],  (const float*)d_in[17], (const float*)d_in[25]};
    const float* w_out[3] = {(const float*)d_in[10], (const float*)d_in[18], (const float*)d_in[26]};
    const float* b_out[3] = {(const float*)d_in[11], (const float*)d_in[19], (const float*)d_in[27]};
    const float* head_w   = (const float*)d_in[28];
    const float* head_b   = (const float*)d_in[29];
    float* out = (float*)d_out;

    float *hbuf, *aggbuf, *zbuf, *poolbuf;
    cudaGetSymbolAddress((void**)&hbuf, g_h);
    cudaGetSymbolAddress((void**)&aggbuf, g_agg);
    cudaGetSymbolAddress((void**)&zbuf, g_z);
    cudaGetSymbolAddress((void**)&poolbuf, g_pool);

    const int TB = 256;
    const int GB = 512;
    const int gemm_blocks = (N_NODES + 127) / 128;

    // ---- layer 1 (Din=32) ----
    copy_x_kernel<<<(N_NODES * DIN0 / 4 + TB - 1) / TB, TB>>>(x);
    {
        int tot = N_EDGES * (DIN0 / 4);
        edge_kernel<DIN0><<<(tot + TB - 1) / TB, TB>>>(x, ei, aggbuf);
    }
    gemm_kernel<DIN0, true, false><<<gemm_blocks, GB>>>(
        aggbuf, w_in[0], b_in[0], gam[0], bet[0], rme[0], rva[0], zbuf, nullptr);
    gemm_kernel<HID, false, true><<<gemm_blocks, GB>>>(
        zbuf, w_out[0], b_out[0], nullptr, nullptr, nullptr, nullptr, hbuf, aggbuf);

    // ---- layer 2 ----
    {
        int tot = N_EDGES * (HID / 4);
        edge_kernel<HID><<<(tot + TB - 1) / TB, TB>>>(hbuf, ei, aggbuf);
    }
    gemm_kernel<HID, true, false><<<gemm_blocks, GB>>>(
        aggbuf, w_in[1], b_in[1], gam[1], bet[1], rme[1], rva[1], zbuf, nullptr);
    gemm_kernel<HID, false, true><<<gemm_blocks, GB>>>(
        zbuf, w_out[1], b_out[1], nullptr, nullptr, nullptr, nullptr, hbuf, aggbuf);

    // ---- layer 3 ----
    {
        int tot = N_EDGES * (HID / 4);
        edge_kernel<HID><<<(tot + TB - 1) / TB, TB>>>(hbuf, ei, aggbuf);
    }
    gemm_kernel<HID, true, false><<<gemm_blocks, GB>>>(
        aggbuf, w_in[2], b_in[2], gam[2], bet[2], rme[2], rva[2], zbuf, nullptr);
    gemm_kernel<HID, false, false><<<gemm_blocks, GB>>>(
        zbuf, w_out[2], b_out[2], nullptr, nullptr, nullptr, nullptr, hbuf, nullptr);

    // ---- pooling + head ----
    pool_kernel<<<N_GRAPHS, 96>>>(bat, poolbuf);
    head_kernel<<<1, 256>>>(rtg, head_w, head_b, poolbuf, out);
}

// round 10
// speedup vs baseline: 1.1158x; 1.1158x over previous
#include <cuda_runtime.h>
#include <cuda_bf16.h>
#include <stdint.h>

#define N_NODES 50000
#define N_EDGES 800000
#define N_GRAPHS 256
#define DIN0 32
#define HID 96
#define BN_EPS 1e-5f

// ---------------- device scratch (static, allowed) ----------------
__device__ float g_h[(size_t)N_NODES * HID];
__device__ float g_agg[(size_t)N_NODES * HID];
__device__ float g_z[(size_t)N_NODES * HID];
__device__ float g_pool[N_GRAPHS * HID];

// vectorized fire-and-forget global reduction (sm_90+)
__device__ __forceinline__ void red_add_v4(float* addr, float4 v) {
    asm volatile("red.global.add.v4.f32 [%0], {%1, %2, %3, %4};"
                 :: "l"(addr), "f"(v.x), "f"(v.y), "f"(v.z), "f"(v.w)
                 : "memory");
}

__device__ __forceinline__ float to_tf32(float x) {
    uint32_t u;
    asm("cvt.rna.tf32.f32 %0, %1;" : "=r"(u) : "f"(x));
    return __uint_as_float(u);
}

__device__ __forceinline__ void mma_tf32(float* c, uint32_t a0, uint32_t a1,
                                         uint32_t a2, uint32_t a3,
                                         uint32_t b0, uint32_t b1) {
    asm volatile(
        "mma.sync.aligned.m16n8k8.row.col.f32.tf32.tf32.f32 "
        "{%0,%1,%2,%3}, {%4,%5,%6,%7}, {%8,%9}, {%0,%1,%2,%3};"
        : "+f"(c[0]), "+f"(c[1]), "+f"(c[2]), "+f"(c[3])
        : "r"(a0), "r"(a1), "r"(a2), "r"(a3), "r"(b0), "r"(b1));
}

// ---------------- small kernels ----------------
__global__ void copy_x_kernel(const float* __restrict__ x) {
    int i = blockIdx.x * blockDim.x + threadIdx.x;
    int total = N_NODES * DIN0 / 4;
    if (i < total) ((float4*)g_agg)[i] = ((const float4*)x)[i];
}

// edge scatter: agg[dst] += h[src], one red.v4 per (edge, lane)
template<int DIN>
__global__ void edge_kernel(const float* __restrict__ h,
                            const int* __restrict__ ei,
                            float* __restrict__ agg) {
    const int VPR = DIN / 4;
    int t = blockIdx.x * blockDim.x + threadIdx.x;
    int e = t / VPR;
    int lane = t - e * VPR;
    if (e >= N_EDGES) return;
    int s = __ldg(&ei[e]);
    int d = __ldg(&ei[N_EDGES + e]);
    float4 v = *(const float4*)(h + (size_t)s * DIN + lane * 4);
    red_add_v4(agg + (size_t)d * DIN + lane * 4, v);
}

// ---------------- TF32 tensor-core GEMM: out = epi(A[N x DIN] @ W[DIN x 96]) --
// 256 threads = 8 warps. Block tile M=128 x N=96.
// Warp (mw=warp&3, nw=warp>>2): 32-row slab (2 m16 frags) x 48-col slab (6 n8 frags).
// A k-chunks of 8, transposed in smem As[k][row] (stride 136), double-buffered.
// W transposed in smem Wt[n][k] (stride DIN+4).
// __launch_bounds__(256,3): caps regs at 85 -> 3 blocks/SM (24 warps).
template<int DIN, bool HAS_BN, bool DUAL>
__global__ void __launch_bounds__(256, 3) gemm_kernel(
    const float* __restrict__ A, const float* __restrict__ W,
    const float* __restrict__ bias,
    const float* __restrict__ gamma, const float* __restrict__ beta,
    const float* __restrict__ rmean, const float* __restrict__ rvar,
    float* __restrict__ out, float* __restrict__ out2)
{
    constexpr int H = 96;
    constexpr int NKC = DIN / 8;
    constexpr int WSTR = DIN + 4;
    __shared__ float Wt[H * WSTR];          // W^T: Wt[n][k]
    __shared__ float As[2][8][136];         // A^T chunk: As[k][row]

    const int tid  = threadIdx.x;
    const int warp = tid >> 5;
    const int lane = tid & 31;
    const int g    = lane >> 2;             // 0..7
    const int tg   = lane & 3;              // 0..3
    const int mw   = warp & 3;              // 0..3 -> 32-row slab
    const int nw   = warp >> 2;             // 0..1 -> 48-col slab
    const int row0 = blockIdx.x * 128;

    // load W transposed + tf32-rounded
    for (int i = tid; i < DIN * H; i += 256) {
        int k = i / H, n = i - k * H;
        Wt[n * WSTR + k] = to_tf32(W[i]);
    }

    const int r  = tid & 127;
    const int kv = tid >> 7;                // 0..1 -> k sub-offset 4*kv

    float acc[2][6][4];
    #pragma unroll
    for (int mi = 0; mi < 2; mi++)
        #pragma unroll
        for (int ni = 0; ni < 6; ni++)
            #pragma unroll
            for (int q = 0; q < 4; q++) acc[mi][ni][q] = 0.f;

    // stage chunk 0
    {
        int gr = row0 + r;
        float4 v = (gr < N_NODES)
            ? *(const float4*)(A + (size_t)gr * DIN + kv * 4)
            : make_float4(0.f, 0.f, 0.f, 0.f);
        As[0][kv * 4 + 0][r] = to_tf32(v.x);
        As[0][kv * 4 + 1][r] = to_tf32(v.y);
        As[0][kv * 4 + 2][r] = to_tf32(v.z);
        As[0][kv * 4 + 3][r] = to_tf32(v.w);
    }
    __syncthreads();

    int buf = 0;
    for (int kt = 0; kt < NKC; kt++) {
        float4 nv;
        if (kt + 1 < NKC) {
            int gr = row0 + r;
            nv = (gr < N_NODES)
                ? *(const float4*)(A + (size_t)gr * DIN + (kt + 1) * 8 + kv * 4)
                : make_float4(0.f, 0.f, 0.f, 0.f);
        }

        const int kb = kt * 8;
        uint32_t bf[6][2];
        #pragma unroll
        for (int ni = 0; ni < 6; ni++) {
            int n = nw * 48 + ni * 8 + g;
            bf[ni][0] = __float_as_uint(Wt[n * WSTR + kb + tg]);
            bf[ni][1] = __float_as_uint(Wt[n * WSTR + kb + tg + 4]);
        }
        #pragma unroll
        for (int mi = 0; mi < 2; mi++) {
            int ra = mw * 32 + mi * 16 + g;
            uint32_t a0 = __float_as_uint(As[buf][tg][ra]);
            uint32_t a1 = __float_as_uint(As[buf][tg][ra + 8]);
            uint32_t a2 = __float_as_uint(As[buf][tg + 4][ra]);
            uint32_t a3 = __float_as_uint(As[buf][tg + 4][ra + 8]);
            #pragma unroll
            for (int ni = 0; ni < 6; ni++)
                mma_tf32(acc[mi][ni], a0, a1, a2, a3, bf[ni][0], bf[ni][1]);
        }

        if (kt + 1 < NKC) {
            As[buf ^ 1][kv * 4 + 0][r] = to_tf32(nv.x);
            As[buf ^ 1][kv * 4 + 1][r] = to_tf32(nv.y);
            As[buf ^ 1][kv * 4 + 2][r] = to_tf32(nv.z);
            As[buf ^ 1][kv * 4 + 3][r] = to_tf32(nv.w);
            __syncthreads();
        }
        buf ^= 1;
    }

    // epilogue: per-thread cols = nw*48 + ni*8 + 2*tg (+1)
    float sc[6][2], sh[6][2];
    #pragma unroll
    for (int ni = 0; ni < 6; ni++)
        #pragma unroll
        for (int jj = 0; jj < 2; jj++) {
            int c = nw * 48 + ni * 8 + 2 * tg + jj;
            if (HAS_BN) {
                float s = gamma[c] * rsqrtf(rvar[c] + BN_EPS);
                sc[ni][jj] = s;
                sh[ni][jj] = (bias[c] - rmean[c]) * s + beta[c];
            } else {
                sc[ni][jj] = 1.f;
                sh[ni][jj] = bias[c];
            }
        }

    #pragma unroll
    for (int mi = 0; mi < 2; mi++) {
        int ra = row0 + mw * 32 + mi * 16 + g;
        int rb = ra + 8;
        #pragma unroll
        for (int ni = 0; ni < 6; ni++) {
            int col = nw * 48 + ni * 8 + 2 * tg;
            if (ra < N_NODES) {
                float2 o;
                o.x = fmaxf(fmaf(acc[mi][ni][0], sc[ni][0], sh[ni][0]), 0.f);
                o.y = fmaxf(fmaf(acc[mi][ni][1], sc[ni][1], sh[ni][1]), 0.f);
                *(float2*)(out + (size_t)ra * H + col) = o;
                if (DUAL) *(float2*)(out2 + (size_t)ra * H + col) = o;
            }
            if (rb < N_NODES) {
                float2 o;
                o.x = fmaxf(fmaf(acc[mi][ni][2], sc[ni][0], sh[ni][0]), 0.f);
                o.y = fmaxf(fmaf(acc[mi][ni][3], sc[ni][1], sh[ni][1]), 0.f);
                *(float2*)(out + (size_t)rb * H + col) = o;
                if (DUAL) *(float2*)(out2 + (size_t)rb * H + col) = o;
            }
        }
    }
}

// ---------------- pooling (batch sorted -> segment sums, no atomics) ----------
__global__ void __launch_bounds__(96) pool_kernel(const int* __restrict__ batch,
                                                  float* __restrict__ pool) {
    int b = blockIdx.x;
    int c = threadIdx.x;
    int lo = 0, hi = N_NODES;
    while (lo < hi) { int m = (lo + hi) >> 1; if (batch[m] < b) lo = m + 1; else hi = m; }
    int start = lo;
    hi = N_NODES;
    while (lo < hi) { int m = (lo + hi) >> 1; if (batch[m] < b + 1) lo = m + 1; else hi = m; }
    int end = lo;

    float acc = 0.f;
    for (int n = start; n < end; n++)
        acc += g_h[(size_t)n * HID + c];
    pool[b * HID + c] = acc;
}

__global__ void head_kernel(const int* __restrict__ r_target,
                            const float* __restrict__ head_w,
                            const float* __restrict__ head_b,
                            const float* __restrict__ pool,
                            float* __restrict__ out) {
    int b = threadIdx.x;
    if (b >= N_GRAPHS) return;
    int t = r_target[b];
    const float4* w = (const float4*)(head_w + (size_t)t * HID);
    const float4* p = (const float4*)(pool + (size_t)b * HID);
    float acc = 0.f;
    #pragma unroll
    for (int k = 0; k < HID / 4; k++) {
        float4 wv = w[k], pv = p[k];
        acc = fmaf(pv.x, wv.x, acc);
        acc = fmaf(pv.y, wv.y, acc);
        acc = fmaf(pv.z, wv.z, acc);
        acc = fmaf(pv.w, wv.w, acc);
    }
    out[b] = acc + head_b[t];
}

// ---------------- launch ----------------
extern "C" void kernel_launch(void* const* d_in, const int* in_sizes, int n_in,
                              void* d_out, int out_size) {
    const float* x    = (const float*)d_in[0];
    const int*   ei   = (const int*)d_in[1];
    const int*   bat  = (const int*)d_in[2];
    const int*   rtg  = (const int*)d_in[3];

    const float* w_in[3]  = {(const float*)d_in[4],  (const float*)d_in[12], (const float*)d_in[20]};
    const float* b_in[3]  = {(const float*)d_in[5],  (const float*)d_in[13], (const float*)d_in[21]};
    const float* gam[3]   = {(const float*)d_in[6],  (const float*)d_in[14], (const float*)d_in[22]};
    const float* bet[3]   = {(const float*)d_in[7],  (const float*)d_in[15], (const float*)d_in[23]};
    const float* rme[3]   = {(const float*)d_in[8],  (const float*)d_in[16], (const float*)d_in[24]};
    const float* rva[3]   = {(const float*)d_in[9],  (const float*)d_in[17], (const float*)d_in[25]};
    const float* w_out[3] = {(const float*)d_in[10], (const float*)d_in[18], (const float*)d_in[26]};
    const float* b_out[3] = {(const float*)d_in[11], (const float*)d_in[19], (const float*)d_in[27]};
    const float* head_w   = (const float*)d_in[28];
    const float* head_b   = (const float*)d_in[29];
    float* out = (float*)d_out;

    float *hbuf, *aggbuf, *zbuf, *poolbuf;
    cudaGetSymbolAddress((void**)&hbuf, g_h);
    cudaGetSymbolAddress((void**)&aggbuf, g_agg);
    cudaGetSymbolAddress((void**)&zbuf, g_z);
    cudaGetSymbolAddress((void**)&poolbuf, g_pool);

    const int TB = 256;
    const int GB = 256;
    const int gemm_blocks = (N_NODES + 127) / 128;

    // ---- layer 1 (Din=32) ----
    copy_x_kernel<<<(N_NODES * DIN0 / 4 + TB - 1) / TB, TB>>>(x);
    {
        int tot = N_EDGES * (DIN0 / 4);
        edge_kernel<DIN0><<<(tot + TB - 1) / TB, TB>>>(x, ei, aggbuf);
    }
    gemm_kernel<DIN0, true, false><<<gemm_blocks, GB>>>(
        aggbuf, w_in[0], b_in[0], gam[0], bet[0], rme[0], rva[0], zbuf, nullptr);
    gemm_kernel<HID, false, true><<<gemm_blocks, GB>>>(
        zbuf, w_out[0], b_out[0], nullptr, nullptr, nullptr, nullptr, hbuf, aggbuf);

    // ---- layer 2 ----
    {
        int tot = N_EDGES * (HID / 4);
        edge_kernel<HID><<<(tot + TB - 1) / TB, TB>>>(hbuf, ei, aggbuf);
    }
    gemm_kernel<HID, true, false><<<gemm_blocks, GB>>>(
        aggbuf, w_in[1], b_in[1], gam[1], bet[1], rme[1], rva[1], zbuf, nullptr);
    gemm_kernel<HID, false, true><<<gemm_blocks, GB>>>(
        zbuf, w_out[1], b_out[1], nullptr, nullptr, nullptr, nullptr, hbuf, aggbuf);

    // ---- layer 3 ----
    {
        int tot = N_EDGES * (HID / 4);
        edge_kernel<HID><<<(tot + TB - 1) / TB, TB>>>(hbuf, ei, aggbuf);
    }
    gemm_kernel<HID, true, false><<<gemm_blocks, GB>>>(
        aggbuf, w_in[2], b_in[2], gam[2], bet[2], rme[2], rva[2], zbuf, nullptr);
    gemm_kernel<HID, false, false><<<gemm_blocks, GB>>>(
        zbuf, w_out[2], b_out[2], nullptr, nullptr, nullptr, nullptr, hbuf, nullptr);

    // ---- pooling + head ----
    pool_kernel<<<N_GRAPHS, 96>>>(bat, poolbuf);
    head_kernel<<<1, 256>>>(rtg, head_w, head_b, poolbuf, out);
}